// round 1
// baseline (speedup 1.0000x reference)
#include <cuda_runtime.h>
#include <math.h>

#define BB 2
#define TT 2048
#define CC 1024
#define HH 16
#define DD 64
#define C3 3072
#define MM (BB*TT)          // 4096
#define YELEMS (BB*TT*CC)   // 4194304

// scratch (static device arrays: allocation-free)
__device__ float g_qkv[MM * C3];   // [B*T, 3C]
__device__ float g_yatt[MM * CC];  // [B*T, C] head-interleaved, ready for proj GEMM

// ---------------------------------------------------------------------------
// Tiled fp32 GEMM with bias: out[M,N] = A[M,K] @ W[K,N] + bias[N]
// 128x128 block tile, K-step 8, 256 threads, 8x8 per-thread microtile.
// M,N,K all multiples of 128/8 here -> no edge guards.
// ---------------------------------------------------------------------------
__global__ __launch_bounds__(256) void sgemm_bias(
    const float* __restrict__ A, const float* __restrict__ W,
    const float* __restrict__ bias, float* __restrict__ out,
    int M, int N, int K)
{
    __shared__ float As[8][128];
    __shared__ float Bs[8][128];
    const int tid = threadIdx.x;
    const int m0 = blockIdx.y * 128, n0 = blockIdx.x * 128;
    const int arow = tid >> 1, ac = (tid & 1) * 4;
    const int brow = tid >> 5, bc = (tid & 31) * 4;
    const int ty = tid >> 4, tx = tid & 15;

    float c[8][8];
#pragma unroll
    for (int i = 0; i < 8; i++)
#pragma unroll
        for (int j = 0; j < 8; j++) c[i][j] = 0.0f;

    for (int k0 = 0; k0 < K; k0 += 8) {
        float4 av = *(const float4*)&A[(size_t)(m0 + arow) * K + k0 + ac];
        float4 bv = *(const float4*)&W[(size_t)(k0 + brow) * N + n0 + bc];
        __syncthreads();
        As[ac + 0][arow] = av.x;
        As[ac + 1][arow] = av.y;
        As[ac + 2][arow] = av.z;
        As[ac + 3][arow] = av.w;
        *(float4*)&Bs[brow][bc] = bv;
        __syncthreads();
#pragma unroll
        for (int kk = 0; kk < 8; kk++) {
            float4 a0 = *(const float4*)&As[kk][ty * 8];
            float4 a1 = *(const float4*)&As[kk][ty * 8 + 4];
            float4 b0 = *(const float4*)&Bs[kk][tx * 8];
            float4 b1 = *(const float4*)&Bs[kk][tx * 8 + 4];
            float a[8] = {a0.x, a0.y, a0.z, a0.w, a1.x, a1.y, a1.z, a1.w};
            float b[8] = {b0.x, b0.y, b0.z, b0.w, b1.x, b1.y, b1.z, b1.w};
#pragma unroll
            for (int i = 0; i < 8; i++)
#pragma unroll
                for (int j = 0; j < 8; j++) c[i][j] += a[i] * b[j];
        }
    }

#pragma unroll
    for (int i = 0; i < 8; i++) {
        int row = m0 + ty * 8 + i;
        int col = n0 + tx * 8;
        float4 o0, o1;
        o0.x = c[i][0] + bias[col + 0];
        o0.y = c[i][1] + bias[col + 1];
        o0.z = c[i][2] + bias[col + 2];
        o0.w = c[i][3] + bias[col + 3];
        o1.x = c[i][4] + bias[col + 4];
        o1.y = c[i][5] + bias[col + 5];
        o1.z = c[i][6] + bias[col + 6];
        o1.w = c[i][7] + bias[col + 7];
        *(float4*)&out[(size_t)row * N + col] = o0;
        *(float4*)&out[(size_t)row * N + col + 4] = o1;
    }
}

// ---------------------------------------------------------------------------
// Flash-style attention with adaptive span+wave mask.
// Reference: weighted = exp(att - rowmax) * mask; att = weighted / sum(weighted)
// (normalization-invariant -> fully-masked key tiles can be skipped exactly).
// Grid: (T/64, H, B), 256 threads. Tiles 64x64. Dynamic smem 3*64*68 floats.
// Thread (ty,tx): S rows {4ty+ii}, S cols {tx+16jj}.
// ---------------------------------------------------------------------------
__global__ __launch_bounds__(256) void attn_kernel(
    const float* __restrict__ qkv,
    const float* __restrict__ span_p, const float* __restrict__ period_w,
    const float* __restrict__ ratio_w, float* __restrict__ yout)
{
    extern __shared__ float sm[];
    const int STR = 68;
    float* Qs = sm;                 // 64 x 68
    float* Ks = sm + 64 * STR;      // 64 x 68 (aliased as Ps after S-compute)
    float* Vs = sm + 2 * 64 * STR;  // 64 x 68

    const int tid = threadIdx.x;
    const int ty = tid >> 4, tx = tid & 15;
    const int i0 = blockIdx.x * 64;
    const int h = blockIdx.y;
    const int b = blockIdx.z;

    // per-head mask constants (matches jax.nn.sigmoid etc.)
    const float span   = 2048.0f / (1.0f + __expf(-span_p[h]));
    const float period = 2.0f + 2.0f / (1.0f + __expf(-period_w[h]));
    const float ratio  = -0.25f + 0.5f / (1.0f + __expf(-ratio_w[h]));
    const float amp    = period * 0.25f;
    const float offs   = period * ratio;

    // load Q tile, pre-scaled by 1/sqrt(64)
    {
        int row = tid >> 2;
        int dbase = (tid & 3) * 16;
        const float* src = &qkv[(size_t)(b * TT + i0 + row) * C3 + h * 64 + dbase];
#pragma unroll
        for (int u = 0; u < 4; u++) {
            float4 v = *(const float4*)&src[u * 4];
            v.x *= 0.125f; v.y *= 0.125f; v.z *= 0.125f; v.w *= 0.125f;
            *(float4*)&Qs[row * STR + dbase + u * 4] = v;
        }
    }

    float mrow[4], lrow[4], acc[4][4];
#pragma unroll
    for (int i = 0; i < 4; i++) {
        mrow[i] = -1e30f; lrow[i] = 0.0f;
#pragma unroll
        for (int j = 0; j < 4; j++) acc[i][j] = 0.0f;
    }

    // span cutoff: mask_pos == 0 for rel >= span + R(=32). Conservative margin.
    int jstart = 0;
    float thr = (float)i0 - 96.0f - span;
    if (thr > 0.0f) jstart = ((int)thr / 64) * 64;

    for (int j0 = jstart; j0 <= i0; j0 += 64) {
        __syncthreads();  // previous PV reads done before K/V overwrite
        {
            int row = tid >> 2;
            int dbase = (tid & 3) * 16;
            const float* kp = &qkv[(size_t)(b * TT + j0 + row) * C3 + CC + h * 64 + dbase];
            const float* vp = kp + CC;
#pragma unroll
            for (int u = 0; u < 4; u++) {
                *(float4*)&Ks[row * STR + dbase + u * 4] = *(const float4*)&kp[u * 4];
                *(float4*)&Vs[row * STR + dbase + u * 4] = *(const float4*)&vp[u * 4];
            }
        }
        __syncthreads();

        // S = Q @ K^T
        float s[4][4];
#pragma unroll
        for (int i = 0; i < 4; i++)
#pragma unroll
            for (int j = 0; j < 4; j++) s[i][j] = 0.0f;
#pragma unroll
        for (int d4 = 0; d4 < 16; d4++) {
            float4 q[4], k[4];
#pragma unroll
            for (int ii = 0; ii < 4; ii++) q[ii] = *(const float4*)&Qs[(4 * ty + ii) * STR + 4 * d4];
#pragma unroll
            for (int jj = 0; jj < 4; jj++) k[jj] = *(const float4*)&Ks[(tx + 16 * jj) * STR + 4 * d4];
#pragma unroll
            for (int ii = 0; ii < 4; ii++)
#pragma unroll
                for (int jj = 0; jj < 4; jj++)
                    s[ii][jj] += q[ii].x * k[jj].x + q[ii].y * k[jj].y +
                                 q[ii].z * k[jj].z + q[ii].w * k[jj].w;
        }
        __syncthreads();  // Ks reads complete; safe to overwrite with P

        float* Ps = Ks;
#pragma unroll
        for (int ii = 0; ii < 4; ii++) {
            const int i = i0 + 4 * ty + ii;
            float rmax = -1e30f;
            float sv[4];
#pragma unroll
            for (int jj = 0; jj < 4; jj++) {
                int j = j0 + tx + 16 * jj;
                sv[jj] = (j <= i) ? s[ii][jj] : -1e30f;
                rmax = fmaxf(rmax, sv[jj]);
            }
#pragma unroll
            for (int o = 8; o > 0; o >>= 1)
                rmax = fmaxf(rmax, __shfl_xor_sync(0xffffffffu, rmax, o));
            float mnew = fmaxf(mrow[ii], rmax);
            float corr = __expf(mrow[ii] - mnew);
            mrow[ii] = mnew;
            float rsum = 0.0f;
#pragma unroll
            for (int jj = 0; jj < 4; jj++) {
                int j = j0 + tx + 16 * jj;
                float p = 0.0f;
                if (j <= i) {
                    float relf = (float)(i - j);
                    float mpos = (32.0f - relf + span) * 0.03125f;
                    mpos = fminf(fmaxf(mpos, 0.0f), 1.0f);
                    float wave = 0.5f * (cosf(6.283185307179586f * relf / period) + 1.0f) * amp
                                 + 0.5f + offs;
                    wave = fminf(fmaxf(wave, 0.0f), 1.0f);
                    p = __expf(sv[jj] - mnew) * (mpos * wave);
                }
                rsum += p;
                Ps[(4 * ty + ii) * STR + tx + 16 * jj] = p;
            }
#pragma unroll
            for (int o = 8; o > 0; o >>= 1)
                rsum += __shfl_xor_sync(0xffffffffu, rsum, o);
            lrow[ii] = lrow[ii] * corr + rsum;
#pragma unroll
            for (int jj = 0; jj < 4; jj++) acc[ii][jj] *= corr;
        }
        __syncthreads();  // P visible to all

        // O += P @ V
#pragma unroll 4
        for (int jd0 = 0; jd0 < 64; jd0 += 4) {
            float pr[4][4];
#pragma unroll
            for (int ii = 0; ii < 4; ii++) {
                float4 p4 = *(const float4*)&Ps[(4 * ty + ii) * STR + jd0];
                pr[ii][0] = p4.x; pr[ii][1] = p4.y; pr[ii][2] = p4.z; pr[ii][3] = p4.w;
            }
#pragma unroll
            for (int u = 0; u < 4; u++) {
                float vv[4];
#pragma unroll
                for (int jj = 0; jj < 4; jj++) vv[jj] = Vs[(jd0 + u) * STR + tx + 16 * jj];
#pragma unroll
                for (int ii = 0; ii < 4; ii++)
#pragma unroll
                    for (int jj = 0; jj < 4; jj++) acc[ii][jj] += pr[ii][u] * vv[jj];
            }
        }
    }

    // epilogue: normalize and write y_att[B*T, C] (head-interleaved)
#pragma unroll
    for (int ii = 0; ii < 4; ii++) {
        const int i = i0 + 4 * ty + ii;
        float inv = 1.0f / lrow[ii];
#pragma unroll
        for (int jj = 0; jj < 4; jj++) {
            int col = tx + 16 * jj;
            yout[(size_t)(b * TT + i) * CC + h * 64 + col] = acc[ii][jj] * inv;
        }
    }
}

// ---------------------------------------------------------------------------
// span_loss scalar
// ---------------------------------------------------------------------------
__global__ void loss_kernel(const float* __restrict__ sp, const float* __restrict__ pw,
                            const float* __restrict__ rw, float* __restrict__ out,
                            int out_size)
{
    if (threadIdx.x == 0 && blockIdx.x == 0 && out_size > YELEMS) {
        float a = 0.0f;
        for (int h = 0; h < HH; h++) {
            float span   = 2048.0f / (1.0f + expf(-sp[h]));
            float period = 2.0f + 2.0f / (1.0f + expf(-pw[h]));
            float ratio  = -0.25f + 0.5f / (1.0f + expf(-rw[h]));
            float lt = 1.0f / period + 2.0f * ratio - 0.25f + 0.5f;
            a += (span + 32.0f) * lt;
        }
        out[YELEMS] = 2e-6f * a / (float)HH;
    }
}

// ---------------------------------------------------------------------------
extern "C" void kernel_launch(void* const* d_in, const int* in_sizes, int n_in,
                              void* d_out, int out_size)
{
    const float* x       = (const float*)d_in[0];
    const float* w_attn  = (const float*)d_in[1];
    const float* b_attn  = (const float*)d_in[2];
    const float* w_proj  = (const float*)d_in[3];
    const float* b_proj  = (const float*)d_in[4];
    const float* span_p  = (const float*)d_in[5];
    const float* per_w   = (const float*)d_in[6];
    const float* rat_w   = (const float*)d_in[7];
    float* out = (float*)d_out;

    float* qkvp = nullptr;
    float* yattp = nullptr;
    cudaGetSymbolAddress((void**)&qkvp, g_qkv);
    cudaGetSymbolAddress((void**)&yattp, g_yatt);

    const int ATTN_SMEM = 3 * 64 * 68 * (int)sizeof(float);  // 52224
    cudaFuncSetAttribute(attn_kernel, cudaFuncAttributeMaxDynamicSharedMemorySize, ATTN_SMEM);

    // 1. QKV projection
    sgemm_bias<<<dim3(C3 / 128, MM / 128), 256>>>(x, w_attn, b_attn, qkvp, MM, C3, CC);
    // 2. attention
    attn_kernel<<<dim3(TT / 64, HH, BB), 256, ATTN_SMEM>>>(qkvp, span_p, per_w, rat_w, yattp);
    // 3. output projection (writes y directly into d_out)
    sgemm_bias<<<dim3(CC / 128, MM / 128), 256>>>(yattp, w_proj, b_proj, out, MM, CC, CC);
    // 4. span loss scalar
    loss_kernel<<<1, 32>>>(span_p, per_w, rat_w, out, out_size);
}

// round 3
// speedup vs baseline: 1.1669x; 1.1669x over previous
#include <cuda_runtime.h>
#include <math.h>

#define BB 2
#define TT 2048
#define CC 1024
#define HH 16
#define DD 64
#define C3 3072
#define MM (BB*TT)          // 4096
#define YELEMS (BB*TT*CC)   // 4194304

// scratch (static device arrays: allocation-free)
__device__ float g_qkv[MM * C3];   // [B*T, 3C]
__device__ float g_yatt[MM * CC];  // [B*T, C] head-interleaved, ready for proj GEMM

__device__ __forceinline__ unsigned f2tf32(float x) {
    unsigned r;
    asm("cvt.rna.tf32.f32 %0, %1;" : "=r"(r) : "f"(x));
    return r;
}

__device__ __forceinline__ void mma_tf32(float c[4], unsigned a0, unsigned a1,
                                         unsigned a2, unsigned a3,
                                         unsigned b0, unsigned b1) {
    asm volatile(
        "mma.sync.aligned.m16n8k8.row.col.f32.tf32.tf32.f32 "
        "{%0,%1,%2,%3}, {%4,%5,%6,%7}, {%8,%9}, {%0,%1,%2,%3};"
        : "+f"(c[0]), "+f"(c[1]), "+f"(c[2]), "+f"(c[3])
        : "r"(a0), "r"(a1), "r"(a2), "r"(a3), "r"(b0), "r"(b1));
}

// ---------------------------------------------------------------------------
// tf32 tensor-core GEMM with bias: out[M,N] = A[M,K] @ W[K,N] + bias[N]
// Block tile 128x128, K-step 32, 256 threads (8 warps), warp tile 32x64.
// A smem: stride 40, k-permuted so fragment cols (tig, tig+4) are an aligned
//         float2 at 2*tig. Conflict-free LDS.64 (verified per-phase).
// B smem: stride 128 with XOR chunk swizzle swz(r)=(r&1)|((r&2)<<1):
//         phys_chunk = chunk ^ swz(row). All LDS.128 16B-aligned and
//         conflict-free (slots (2g)^swz(tig) are injective per phase).
//         n permuted: phys col n' = (n&64) + (n&7)*8 + ((n>>3)&7), so the
//         8 n-atoms a thread needs are contiguous.
// ---------------------------------------------------------------------------
#define ASTR 40

__global__ __launch_bounds__(256) void mma_gemm_bias(
    const float* __restrict__ A, const float* __restrict__ W,
    const float* __restrict__ bias, float* __restrict__ out,
    int M, int N, int K)
{
    __shared__ float As[128 * ASTR];
    __shared__ float Bs[32 * 128];

    const int tid = threadIdx.x;
    const int m0 = blockIdx.y * 128, n0 = blockIdx.x * 128;
    const int lane = tid & 31, w = tid >> 5;
    const int wM = w >> 1, wN = w & 1;          // 4 x 2 warp grid
    const int g = lane >> 2, tig = lane & 3;

    // gmem loader mapping
    const int arow = tid >> 1, ac0 = (tid & 1) * 16;     // A: 128 rows x 32 cols
    const int brow = tid >> 3, bc0 = (tid & 7) * 16;     // B: 32 rows x 128 cols
    const int bswz = (brow & 1) | ((brow & 2) << 1);

    float acc[2][8][4];
#pragma unroll
    for (int i = 0; i < 2; i++)
#pragma unroll
        for (int j = 0; j < 8; j++)
#pragma unroll
            for (int c = 0; c < 4; c++) acc[i][j][c] = 0.0f;

    // fragment-load swizzle for rows (row & 3) == tig (holds for tig and tig+4)
    const int fswz = (tig & 1) | ((tig & 2) << 1);

    for (int k0 = 0; k0 < K; k0 += 32) {
        __syncthreads();
        // load A tile 128x32 (tf32-rounded, permuted k within each 8-group)
        {
            const float* ap = &A[(size_t)(m0 + arow) * K + k0 + ac0];
#pragma unroll
            for (int u = 0; u < 4; u++) {
                float4 v = *(const float4*)&ap[u * 4];
                int kk = ac0 + u * 4;
                float vv[4] = {v.x, v.y, v.z, v.w};
#pragma unroll
                for (int c = 0; c < 4; c++) {
                    int k = kk + c;
                    int p = (k & 7);
                    int col = (k >> 3) * 8 + (((p & 3) << 1) | (p >> 2));
                    As[arow * ASTR + col] = __uint_as_float(f2tf32(vv[c]));
                }
            }
        }
        // load B tile 32x128 (tf32-rounded, n-permuted, chunk-swizzled)
        {
            const float* bp = &W[(size_t)(k0 + brow) * N + n0 + bc0];
#pragma unroll
            for (int u = 0; u < 4; u++) {
                float4 v = *(const float4*)&bp[u * 4];
                int nn = bc0 + u * 4;
                float vv[4] = {v.x, v.y, v.z, v.w};
#pragma unroll
                for (int c = 0; c < 4; c++) {
                    int n = nn + c;
                    int col = (n & 64) + (n & 7) * 8 + ((n >> 3) & 7);
                    int phys = ((col >> 2) ^ bswz) * 4 + (col & 3);
                    Bs[brow * 128 + phys] = __uint_as_float(f2tf32(vv[c]));
                }
            }
        }
        __syncthreads();

#pragma unroll
        for (int ka = 0; ka < 4; ka++) {
            unsigned a[2][4];
#pragma unroll
            for (int i = 0; i < 2; i++) {
                int r = wM * 32 + i * 16 + g;
                float2 v0 = *(const float2*)&As[r * ASTR + ka * 8 + 2 * tig];
                float2 v1 = *(const float2*)&As[(r + 8) * ASTR + ka * 8 + 2 * tig];
                a[i][0] = __float_as_uint(v0.x);
                a[i][1] = __float_as_uint(v1.x);
                a[i][2] = __float_as_uint(v0.y);
                a[i][3] = __float_as_uint(v1.y);
            }
            unsigned b0[8], b1[8];
            {
                int chunk = 16 * wN + 2 * g;               // logical chunk of this thread's 8 floats
                int r0 = (ka * 8 + tig) * 128;
                int r1 = (ka * 8 + tig + 4) * 128;
                float4 p0 = *(const float4*)&Bs[r0 + ((chunk ^ fswz) << 2)];
                float4 p1 = *(const float4*)&Bs[r0 + (((chunk + 1) ^ fswz) << 2)];
                float4 q0 = *(const float4*)&Bs[r1 + ((chunk ^ fswz) << 2)];
                float4 q1 = *(const float4*)&Bs[r1 + (((chunk + 1) ^ fswz) << 2)];
                b0[0] = __float_as_uint(p0.x); b0[1] = __float_as_uint(p0.y);
                b0[2] = __float_as_uint(p0.z); b0[3] = __float_as_uint(p0.w);
                b0[4] = __float_as_uint(p1.x); b0[5] = __float_as_uint(p1.y);
                b0[6] = __float_as_uint(p1.z); b0[7] = __float_as_uint(p1.w);
                b1[0] = __float_as_uint(q0.x); b1[1] = __float_as_uint(q0.y);
                b1[2] = __float_as_uint(q0.z); b1[3] = __float_as_uint(q0.w);
                b1[4] = __float_as_uint(q1.x); b1[5] = __float_as_uint(q1.y);
                b1[6] = __float_as_uint(q1.z); b1[7] = __float_as_uint(q1.w);
            }
#pragma unroll
            for (int i = 0; i < 2; i++)
#pragma unroll
                for (int j = 0; j < 8; j++)
                    mma_tf32(acc[i][j], a[i][0], a[i][1], a[i][2], a[i][3],
                             b0[j], b1[j]);
        }
    }

    // epilogue: C frag layout rows (g, g+8), cols (2tig, 2tig+1)
#pragma unroll
    for (int i = 0; i < 2; i++) {
#pragma unroll
        for (int j = 0; j < 8; j++) {
            int row = m0 + wM * 32 + i * 16 + g;
            int col = n0 + wN * 64 + j * 8 + 2 * tig;
            float bx = bias[col], by = bias[col + 1];
            float2 o0 = {acc[i][j][0] + bx, acc[i][j][1] + by};
            float2 o1 = {acc[i][j][2] + bx, acc[i][j][3] + by};
            *(float2*)&out[(size_t)row * N + col] = o0;
            *(float2*)&out[(size_t)(row + 8) * N + col] = o1;
        }
    }
}

// ---------------------------------------------------------------------------
// Flash-style attention with adaptive span+wave mask (unchanged, known-good).
// ---------------------------------------------------------------------------
__global__ __launch_bounds__(256) void attn_kernel(
    const float* __restrict__ qkv,
    const float* __restrict__ span_p, const float* __restrict__ period_w,
    const float* __restrict__ ratio_w, float* __restrict__ yout)
{
    extern __shared__ float sm[];
    const int STR = 68;
    float* Qs = sm;                 // 64 x 68
    float* Ks = sm + 64 * STR;      // 64 x 68 (aliased as Ps after S-compute)
    float* Vs = sm + 2 * 64 * STR;  // 64 x 68

    const int tid = threadIdx.x;
    const int ty = tid >> 4, tx = tid & 15;
    const int i0 = blockIdx.x * 64;
    const int h = blockIdx.y;
    const int b = blockIdx.z;

    const float span   = 2048.0f / (1.0f + __expf(-span_p[h]));
    const float period = 2.0f + 2.0f / (1.0f + __expf(-period_w[h]));
    const float ratio  = -0.25f + 0.5f / (1.0f + __expf(-ratio_w[h]));
    const float amp    = period * 0.25f;
    const float offs   = period * ratio;

    {
        int row = tid >> 2;
        int dbase = (tid & 3) * 16;
        const float* src = &qkv[(size_t)(b * TT + i0 + row) * C3 + h * 64 + dbase];
#pragma unroll
        for (int u = 0; u < 4; u++) {
            float4 v = *(const float4*)&src[u * 4];
            v.x *= 0.125f; v.y *= 0.125f; v.z *= 0.125f; v.w *= 0.125f;
            *(float4*)&Qs[row * STR + dbase + u * 4] = v;
        }
    }

    float mrow[4], lrow[4], acc[4][4];
#pragma unroll
    for (int i = 0; i < 4; i++) {
        mrow[i] = -1e30f; lrow[i] = 0.0f;
#pragma unroll
        for (int j = 0; j < 4; j++) acc[i][j] = 0.0f;
    }

    int jstart = 0;
    float thr = (float)i0 - 96.0f - span;
    if (thr > 0.0f) jstart = ((int)thr / 64) * 64;

    for (int j0 = jstart; j0 <= i0; j0 += 64) {
        __syncthreads();
        {
            int row = tid >> 2;
            int dbase = (tid & 3) * 16;
            const float* kp = &qkv[(size_t)(b * TT + j0 + row) * C3 + CC + h * 64 + dbase];
            const float* vp = kp + CC;
#pragma unroll
            for (int u = 0; u < 4; u++) {
                *(float4*)&Ks[row * STR + dbase + u * 4] = *(const float4*)&kp[u * 4];
                *(float4*)&Vs[row * STR + dbase + u * 4] = *(const float4*)&vp[u * 4];
            }
        }
        __syncthreads();

        float s[4][4];
#pragma unroll
        for (int i = 0; i < 4; i++)
#pragma unroll
            for (int j = 0; j < 4; j++) s[i][j] = 0.0f;
#pragma unroll
        for (int d4 = 0; d4 < 16; d4++) {
            float4 q[4], k[4];
#pragma unroll
            for (int ii = 0; ii < 4; ii++) q[ii] = *(const float4*)&Qs[(4 * ty + ii) * STR + 4 * d4];
#pragma unroll
            for (int jj = 0; jj < 4; jj++) k[jj] = *(const float4*)&Ks[(tx + 16 * jj) * STR + 4 * d4];
#pragma unroll
            for (int ii = 0; ii < 4; ii++)
#pragma unroll
                for (int jj = 0; jj < 4; jj++)
                    s[ii][jj] += q[ii].x * k[jj].x + q[ii].y * k[jj].y +
                                 q[ii].z * k[jj].z + q[ii].w * k[jj].w;
        }
        __syncthreads();

        float* Ps = Ks;
#pragma unroll
        for (int ii = 0; ii < 4; ii++) {
            const int i = i0 + 4 * ty + ii;
            float rmax = -1e30f;
            float sv[4];
#pragma unroll
            for (int jj = 0; jj < 4; jj++) {
                int j = j0 + tx + 16 * jj;
                sv[jj] = (j <= i) ? s[ii][jj] : -1e30f;
                rmax = fmaxf(rmax, sv[jj]);
            }
#pragma unroll
            for (int o = 8; o > 0; o >>= 1)
                rmax = fmaxf(rmax, __shfl_xor_sync(0xffffffffu, rmax, o));
            float mnew = fmaxf(mrow[ii], rmax);
            float corr = __expf(mrow[ii] - mnew);
            mrow[ii] = mnew;
            float rsum = 0.0f;
#pragma unroll
            for (int jj = 0; jj < 4; jj++) {
                int j = j0 + tx + 16 * jj;
                float p = 0.0f;
                if (j <= i) {
                    float relf = (float)(i - j);
                    float mpos = (32.0f - relf + span) * 0.03125f;
                    mpos = fminf(fmaxf(mpos, 0.0f), 1.0f);
                    float wave = 0.5f * (cosf(6.283185307179586f * relf / period) + 1.0f) * amp
                                 + 0.5f + offs;
                    wave = fminf(fmaxf(wave, 0.0f), 1.0f);
                    p = __expf(sv[jj] - mnew) * (mpos * wave);
                }
                rsum += p;
                Ps[(4 * ty + ii) * STR + tx + 16 * jj] = p;
            }
#pragma unroll
            for (int o = 8; o > 0; o >>= 1)
                rsum += __shfl_xor_sync(0xffffffffu, rsum, o);
            lrow[ii] = lrow[ii] * corr + rsum;
#pragma unroll
            for (int jj = 0; jj < 4; jj++) acc[ii][jj] *= corr;
        }
        __syncthreads();

#pragma unroll 4
        for (int jd0 = 0; jd0 < 64; jd0 += 4) {
            float pr[4][4];
#pragma unroll
            for (int ii = 0; ii < 4; ii++) {
                float4 p4 = *(const float4*)&Ps[(4 * ty + ii) * STR + jd0];
                pr[ii][0] = p4.x; pr[ii][1] = p4.y; pr[ii][2] = p4.z; pr[ii][3] = p4.w;
            }
#pragma unroll
            for (int u = 0; u < 4; u++) {
                float vv[4];
#pragma unroll
                for (int jj = 0; jj < 4; jj++) vv[jj] = Vs[(jd0 + u) * STR + tx + 16 * jj];
#pragma unroll
                for (int ii = 0; ii < 4; ii++)
#pragma unroll
                    for (int jj = 0; jj < 4; jj++) acc[ii][jj] += pr[ii][u] * vv[jj];
            }
        }
    }

#pragma unroll
    for (int ii = 0; ii < 4; ii++) {
        const int i = i0 + 4 * ty + ii;
        float inv = 1.0f / lrow[ii];
#pragma unroll
        for (int jj = 0; jj < 4; jj++) {
            int col = tx + 16 * jj;
            yout[(size_t)(b * TT + i) * CC + h * 64 + col] = acc[ii][jj] * inv;
        }
    }
}

// ---------------------------------------------------------------------------
__global__ void loss_kernel(const float* __restrict__ sp, const float* __restrict__ pw,
                            const float* __restrict__ rw, float* __restrict__ out,
                            int out_size)
{
    if (threadIdx.x == 0 && blockIdx.x == 0 && out_size > YELEMS) {
        float a = 0.0f;
        for (int h = 0; h < HH; h++) {
            float span   = 2048.0f / (1.0f + expf(-sp[h]));
            float period = 2.0f + 2.0f / (1.0f + expf(-pw[h]));
            float ratio  = -0.25f + 0.5f / (1.0f + expf(-rw[h]));
            float lt = 1.0f / period + 2.0f * ratio - 0.25f + 0.5f;
            a += (span + 32.0f) * lt;
        }
        out[YELEMS] = 2e-6f * a / (float)HH;
    }
}

// ---------------------------------------------------------------------------
extern "C" void kernel_launch(void* const* d_in, const int* in_sizes, int n_in,
                              void* d_out, int out_size)
{
    const float* x       = (const float*)d_in[0];
    const float* w_attn  = (const float*)d_in[1];
    const float* b_attn  = (const float*)d_in[2];
    const float* w_proj  = (const float*)d_in[3];
    const float* b_proj  = (const float*)d_in[4];
    const float* span_p  = (const float*)d_in[5];
    const float* per_w   = (const float*)d_in[6];
    const float* rat_w   = (const float*)d_in[7];
    float* out = (float*)d_out;

    float* qkvp = nullptr;
    float* yattp = nullptr;
    cudaGetSymbolAddress((void**)&qkvp, g_qkv);
    cudaGetSymbolAddress((void**)&yattp, g_yatt);

    const int ATTN_SMEM = 3 * 64 * 68 * (int)sizeof(float);  // 52224
    cudaFuncSetAttribute(attn_kernel, cudaFuncAttributeMaxDynamicSharedMemorySize, ATTN_SMEM);

    // 1. QKV projection (tf32 tensor cores)
    mma_gemm_bias<<<dim3(C3 / 128, MM / 128), 256>>>(x, w_attn, b_attn, qkvp, MM, C3, CC);
    // 2. attention
    attn_kernel<<<dim3(TT / 64, HH, BB), 256, ATTN_SMEM>>>(qkvp, span_p, per_w, rat_w, yattp);
    // 3. output projection (tf32 tensor cores, writes y directly into d_out)
    mma_gemm_bias<<<dim3(CC / 128, MM / 128), 256>>>(yattp, w_proj, b_proj, out, MM, CC, CC);
    // 4. span loss scalar
    loss_kernel<<<1, 32>>>(span_p, per_w, rat_w, out, out_size);
}

// round 4
// speedup vs baseline: 1.5481x; 1.3267x over previous
#include <cuda_runtime.h>
#include <math.h>

#define BB 2
#define TT 2048
#define CC 1024
#define HH 16
#define DD 64
#define C3 3072
#define MM (BB*TT)          // 4096
#define YELEMS (BB*TT*CC)   // 4194304

#define BQ 128
#define QPSTR 72

// scratch (static device arrays: allocation-free)
__device__ float g_qkv[MM * C3];   // [B*T, 3C]
__device__ float g_yatt[MM * CC];  // [B*T, C]
__device__ float g_mask[HH * TT];  // [H, rel]

__device__ __forceinline__ unsigned f2tf32(float x) {
    unsigned r;
    asm("cvt.rna.tf32.f32 %0, %1;" : "=r"(r) : "f"(x));
    return r;
}

__device__ __forceinline__ void mma_tf32(float c[4], unsigned a0, unsigned a1,
                                         unsigned a2, unsigned a3,
                                         unsigned b0, unsigned b1) {
    asm volatile(
        "mma.sync.aligned.m16n8k8.row.col.f32.tf32.tf32.f32 "
        "{%0,%1,%2,%3}, {%4,%5,%6,%7}, {%8,%9}, {%0,%1,%2,%3};"
        : "+f"(c[0]), "+f"(c[1]), "+f"(c[2]), "+f"(c[3])
        : "r"(a0), "r"(a1), "r"(a2), "r"(a3), "r"(b0), "r"(b1));
}

// FFMA-only exp2 for z <= 0 (clamped at -80). No MUFU.
__device__ __forceinline__ float fexp2(float z) {
    z = fmaxf(z, -80.0f);
    float r = z + 12582912.0f;                       // round z to nearest int
    int zi = __float_as_int(r) - 0x4B400000;
    float f = z - (r - 12582912.0f);                 // f in [-0.5, 0.5]
    float p = 1.3333558e-3f;
    p = fmaf(p, f, 9.6181291e-3f);
    p = fmaf(p, f, 5.5504109e-2f);
    p = fmaf(p, f, 2.4022651e-1f);
    p = fmaf(p, f, 6.9314718e-1f);
    p = fmaf(p, f, 1.0f);
    return __int_as_float(__float_as_int(p) + (zi << 23));
}

// ---------------------------------------------------------------------------
// tf32 tensor-core GEMM with bias (unchanged from R3, known-good).
// ---------------------------------------------------------------------------
#define ASTR 40

__global__ __launch_bounds__(256) void mma_gemm_bias(
    const float* __restrict__ A, const float* __restrict__ W,
    const float* __restrict__ bias, float* __restrict__ out,
    int M, int N, int K)
{
    __shared__ float As[128 * ASTR];
    __shared__ float Bs[32 * 128];

    const int tid = threadIdx.x;
    const int m0 = blockIdx.y * 128, n0 = blockIdx.x * 128;
    const int lane = tid & 31, w = tid >> 5;
    const int wM = w >> 1, wN = w & 1;
    const int g = lane >> 2, tig = lane & 3;

    const int arow = tid >> 1, ac0 = (tid & 1) * 16;
    const int brow = tid >> 3, bc0 = (tid & 7) * 16;
    const int bswz = (brow & 1) | ((brow & 2) << 1);

    float acc[2][8][4];
#pragma unroll
    for (int i = 0; i < 2; i++)
#pragma unroll
        for (int j = 0; j < 8; j++)
#pragma unroll
            for (int c = 0; c < 4; c++) acc[i][j][c] = 0.0f;

    const int fswz = (tig & 1) | ((tig & 2) << 1);

    for (int k0 = 0; k0 < K; k0 += 32) {
        __syncthreads();
        {
            const float* ap = &A[(size_t)(m0 + arow) * K + k0 + ac0];
#pragma unroll
            for (int u = 0; u < 4; u++) {
                float4 v = *(const float4*)&ap[u * 4];
                int kk = ac0 + u * 4;
                float vv[4] = {v.x, v.y, v.z, v.w};
#pragma unroll
                for (int c = 0; c < 4; c++) {
                    int k = kk + c;
                    int p = (k & 7);
                    int col = (k >> 3) * 8 + (((p & 3) << 1) | (p >> 2));
                    As[arow * ASTR + col] = __uint_as_float(f2tf32(vv[c]));
                }
            }
        }
        {
            const float* bp = &W[(size_t)(k0 + brow) * N + n0 + bc0];
#pragma unroll
            for (int u = 0; u < 4; u++) {
                float4 v = *(const float4*)&bp[u * 4];
                int nn = bc0 + u * 4;
                float vv[4] = {v.x, v.y, v.z, v.w};
#pragma unroll
                for (int c = 0; c < 4; c++) {
                    int n = nn + c;
                    int col = (n & 64) + (n & 7) * 8 + ((n >> 3) & 7);
                    int phys = ((col >> 2) ^ bswz) * 4 + (col & 3);
                    Bs[brow * 128 + phys] = __uint_as_float(f2tf32(vv[c]));
                }
            }
        }
        __syncthreads();

#pragma unroll
        for (int ka = 0; ka < 4; ka++) {
            unsigned a[2][4];
#pragma unroll
            for (int i = 0; i < 2; i++) {
                int r = wM * 32 + i * 16 + g;
                float2 v0 = *(const float2*)&As[r * ASTR + ka * 8 + 2 * tig];
                float2 v1 = *(const float2*)&As[(r + 8) * ASTR + ka * 8 + 2 * tig];
                a[i][0] = __float_as_uint(v0.x);
                a[i][1] = __float_as_uint(v1.x);
                a[i][2] = __float_as_uint(v0.y);
                a[i][3] = __float_as_uint(v1.y);
            }
            unsigned b0[8], b1[8];
            {
                int chunk = 16 * wN + 2 * g;
                int r0 = (ka * 8 + tig) * 128;
                int r1 = (ka * 8 + tig + 4) * 128;
                float4 p0 = *(const float4*)&Bs[r0 + ((chunk ^ fswz) << 2)];
                float4 p1 = *(const float4*)&Bs[r0 + (((chunk + 1) ^ fswz) << 2)];
                float4 q0 = *(const float4*)&Bs[r1 + ((chunk ^ fswz) << 2)];
                float4 q1 = *(const float4*)&Bs[r1 + (((chunk + 1) ^ fswz) << 2)];
                b0[0] = __float_as_uint(p0.x); b0[1] = __float_as_uint(p0.y);
                b0[2] = __float_as_uint(p0.z); b0[3] = __float_as_uint(p0.w);
                b0[4] = __float_as_uint(p1.x); b0[5] = __float_as_uint(p1.y);
                b0[6] = __float_as_uint(p1.z); b0[7] = __float_as_uint(p1.w);
                b1[0] = __float_as_uint(q0.x); b1[1] = __float_as_uint(q0.y);
                b1[2] = __float_as_uint(q0.z); b1[3] = __float_as_uint(q0.w);
                b1[4] = __float_as_uint(q1.x); b1[5] = __float_as_uint(q1.y);
                b1[6] = __float_as_uint(q1.z); b1[7] = __float_as_uint(q1.w);
            }
#pragma unroll
            for (int i = 0; i < 2; i++)
#pragma unroll
                for (int j = 0; j < 8; j++)
                    mma_tf32(acc[i][j], a[i][0], a[i][1], a[i][2], a[i][3],
                             b0[j], b1[j]);
        }
    }

#pragma unroll
    for (int i = 0; i < 2; i++) {
#pragma unroll
        for (int j = 0; j < 8; j++) {
            int row = m0 + wM * 32 + i * 16 + g;
            int col = n0 + wN * 64 + j * 8 + 2 * tig;
            float bx = bias[col], by = bias[col + 1];
            float2 o0 = {acc[i][j][0] + bx, acc[i][j][1] + by};
            float2 o1 = {acc[i][j][2] + bx, acc[i][j][3] + by};
            *(float2*)&out[(size_t)row * N + col] = o0;
            *(float2*)&out[(size_t)(row + 8) * N + col] = o1;
        }
    }
}

// ---------------------------------------------------------------------------
// mask table: g_mask[h][rel] = mpos(rel)*wave(rel)  (rel >= 0)
// ---------------------------------------------------------------------------
__global__ void maskgen(const float* __restrict__ sp, const float* __restrict__ pw,
                        const float* __restrict__ rw, float* __restrict__ mask)
{
    int h = blockIdx.x;
    float span   = 2048.0f / (1.0f + __expf(-sp[h]));
    float period = 2.0f + 2.0f / (1.0f + __expf(-pw[h]));
    float ratio  = -0.25f + 0.5f / (1.0f + __expf(-rw[h]));
    float amp = period * 0.25f, offs = period * ratio;
    for (int rel = threadIdx.x; rel < TT; rel += blockDim.x) {
        float relf = (float)rel;
        float mpos = fminf(fmaxf((32.0f - relf + span) * 0.03125f, 0.0f), 1.0f);
        float wave = 0.5f * (cosf(6.283185307179586f * relf / period) + 1.0f) * amp
                     + 0.5f + offs;
        wave = fminf(fmaxf(wave, 0.0f), 1.0f);
        mask[h * TT + rel] = mpos * wave;
    }
}

// ---------------------------------------------------------------------------
// Tensor-core flash attention: 128 q-rows per block, 64-key tiles.
// 8 warps; warp w owns S/O rows 16w..16w+15 (softmax fully warp-local).
// Q (log2e-prescaled tf32) fragments register-resident; staging smem reused
// for P between S and PV. Mask via precomputed smem table; exp via fexp2.
// ---------------------------------------------------------------------------
__global__ __launch_bounds__(256) void attn_mma(
    const float* __restrict__ qkv, const float* __restrict__ span_p,
    const float* __restrict__ gmask, float* __restrict__ yout)
{
    extern __shared__ float sm[];
    float* QP = sm;                    // 128 x 72 (Q staging, then P)
    float* Ks = sm + BQ * QPSTR;       // 64 x 64 (K^T, d-major, swizzled)
    float* Vs = Ks + 64 * 64;          // 64 x 64 (key-major, swizzled)
    float* MT = Vs + 64 * 64;          // 2048 mask entries

    const int tid = threadIdx.x, lane = tid & 31, w = tid >> 5;
    const int g = lane >> 2, tig = lane & 3;
    const int i0 = ((int)gridDim.x - 1 - (int)blockIdx.x) * BQ;  // big blocks first
    const int h = blockIdx.y, b = blockIdx.z;
    const int R = w * 16;
    const int fswz = (tig & 1) | ((tig & 2) << 1);

    for (int t = tid; t < TT; t += 256) MT[t] = gmask[h * TT + t];

    const float span = 2048.0f / (1.0f + __expf(-span_p[h]));

    // stage Q: scaled by 0.125*log2e, tf32, k-permuted, stride 72
    {
        const float SC = 0.125f * 1.4426950408889634f;
        int row = tid >> 1, cb = (tid & 1) * 32;
        const float* src = &qkv[(size_t)(b * TT + i0 + row) * C3 + h * 64 + cb];
#pragma unroll
        for (int u = 0; u < 8; u++) {
            float4 v = *(const float4*)&src[u * 4];
            float vv[4] = {v.x, v.y, v.z, v.w};
#pragma unroll
            for (int c = 0; c < 4; c++) {
                int k = cb + u * 4 + c;
                int p8 = k & 7;
                int col = (k & ~7) | (((p8 & 3) << 1) | (p8 >> 2));
                QP[row * QPSTR + col] = __uint_as_float(f2tf32(vv[c] * SC));
            }
        }
    }
    __syncthreads();

    // Q fragments (register-resident for all key tiles)
    unsigned qf[8][4];
#pragma unroll
    for (int ks = 0; ks < 8; ks++) {
        float2 v0 = *(const float2*)&QP[(R + g) * QPSTR + 8 * ks + 2 * tig];
        float2 v1 = *(const float2*)&QP[(R + g + 8) * QPSTR + 8 * ks + 2 * tig];
        qf[ks][0] = __float_as_uint(v0.x);
        qf[ks][1] = __float_as_uint(v1.x);
        qf[ks][2] = __float_as_uint(v0.y);
        qf[ks][3] = __float_as_uint(v1.y);
    }

    float O[8][4];
#pragma unroll
    for (int a = 0; a < 8; a++)
#pragma unroll
        for (int c = 0; c < 4; c++) O[a][c] = 0.0f;
    float mr[2] = {-1e30f, -1e30f}, lr[2] = {0.0f, 0.0f};

    int jstart = 0;
    {
        float thr = (float)i0 - span - 96.0f;
        if (thr > 0.0f) jstart = ((int)thr / 64) * 64;
    }

    const int irow[2] = {i0 + R + g, i0 + R + g + 8};

    for (int j0 = jstart; j0 <= i0 + BQ - 64; j0 += 64) {
        __syncthreads();
        // load K^T (transpose) and V tiles, tf32, permuted+swizzled
        {
            int key = tid >> 2, db = (tid & 3) * 16;
            const float* kp = &qkv[(size_t)(b * TT + j0 + key) * C3 + CC + h * 64 + db];
            const float* vp = kp + CC;
            int kswz = (key & 1) | ((key & 2) << 1);
            int pk = ((key & 7) << 3) | (key >> 3);
#pragma unroll
            for (int u = 0; u < 4; u++) {
                float4 kv = *(const float4*)&kp[u * 4];
                float4 vv = *(const float4*)&vp[u * 4];
                float ka[4] = {kv.x, kv.y, kv.z, kv.w};
                float va[4] = {vv.x, vv.y, vv.z, vv.w};
#pragma unroll
                for (int c = 0; c < 4; c++) {
                    int d = db + u * 4 + c;
                    int dswz = (d & 1) | ((d & 2) << 1);
                    int physK = ((((pk >> 2) ^ dswz) << 2) | (pk & 3));
                    Ks[d * 64 + physK] = __uint_as_float(f2tf32(ka[c]));
                    int pd = ((d & 7) << 3) | (d >> 3);
                    int physV = ((((pd >> 2) ^ kswz) << 2) | (pd & 3));
                    Vs[key * 64 + physV] = __uint_as_float(f2tf32(va[c]));
                }
            }
        }
        __syncthreads();

        // S = Q @ K^T (log2-scaled logits)
        float S[8][4];
#pragma unroll
        for (int a = 0; a < 8; a++)
#pragma unroll
            for (int c = 0; c < 4; c++) S[a][c] = 0.0f;
#pragma unroll
        for (int ks = 0; ks < 8; ks++) {
            int r0 = (8 * ks + tig) * 64, r1 = (8 * ks + tig + 4) * 64;
            float4 p0 = *(const float4*)&Ks[r0 + (((2 * g) ^ fswz) << 2)];
            float4 p1 = *(const float4*)&Ks[r0 + (((2 * g + 1) ^ fswz) << 2)];
            float4 q0 = *(const float4*)&Ks[r1 + (((2 * g) ^ fswz) << 2)];
            float4 q1 = *(const float4*)&Ks[r1 + (((2 * g + 1) ^ fswz) << 2)];
            unsigned b0[8], b1[8];
            b0[0] = __float_as_uint(p0.x); b0[1] = __float_as_uint(p0.y);
            b0[2] = __float_as_uint(p0.z); b0[3] = __float_as_uint(p0.w);
            b0[4] = __float_as_uint(p1.x); b0[5] = __float_as_uint(p1.y);
            b0[6] = __float_as_uint(p1.z); b0[7] = __float_as_uint(p1.w);
            b1[0] = __float_as_uint(q0.x); b1[1] = __float_as_uint(q0.y);
            b1[2] = __float_as_uint(q0.z); b1[3] = __float_as_uint(q0.w);
            b1[4] = __float_as_uint(q1.x); b1[5] = __float_as_uint(q1.y);
            b1[6] = __float_as_uint(q1.z); b1[7] = __float_as_uint(q1.w);
#pragma unroll
            for (int a = 0; a < 8; a++)
                mma_tf32(S[a], qf[ks][0], qf[ks][1], qf[ks][2], qf[ks][3],
                         b0[a], b1[a]);
        }

        // online softmax per row-pair + P store (own rows only)
#pragma unroll
        for (int r = 0; r < 2; r++) {
            float tmax = -1e30f;
#pragma unroll
            for (int a = 0; a < 8; a++) {
                tmax = fmaxf(tmax, S[a][2 * r]);
                tmax = fmaxf(tmax, S[a][2 * r + 1]);
            }
            tmax = fmaxf(tmax, __shfl_xor_sync(0xffffffffu, tmax, 1));
            tmax = fmaxf(tmax, __shfl_xor_sync(0xffffffffu, tmax, 2));
            float mnew = fmaxf(mr[r], tmax);
            float corr = fexp2(mr[r] - mnew);
            mr[r] = mnew;
            float rsum = 0.0f;
            int prow = (R + g + 8 * r) * QPSTR;
#pragma unroll
            for (int a = 0; a < 8; a++) {
#pragma unroll
                for (int c = 0; c < 2; c++) {
                    int j = j0 + 8 * a + 2 * tig + c;
                    int rel = irow[r] - j;
                    float p = 0.0f;
                    if (rel >= 0)
                        p = fexp2(S[a][2 * r + c] - mnew) * MT[rel];
                    rsum += p;
                    int p8 = 2 * tig + c;
                    int col = 8 * a + (((p8 & 3) << 1) | (p8 >> 2));
                    QP[prow + col] = __uint_as_float(f2tf32(p));
                }
            }
            rsum += __shfl_xor_sync(0xffffffffu, rsum, 1);
            rsum += __shfl_xor_sync(0xffffffffu, rsum, 2);
            lr[r] = lr[r] * corr + rsum;
#pragma unroll
            for (int a = 0; a < 8; a++) {
                O[a][2 * r] *= corr;
                O[a][2 * r + 1] *= corr;
            }
        }
        __syncwarp();

        // O += P @ V
#pragma unroll
        for (int ks = 0; ks < 8; ks++) {
            float2 v0 = *(const float2*)&QP[(R + g) * QPSTR + 8 * ks + 2 * tig];
            float2 v1 = *(const float2*)&QP[(R + g + 8) * QPSTR + 8 * ks + 2 * tig];
            unsigned a0 = __float_as_uint(v0.x), a1 = __float_as_uint(v1.x);
            unsigned a2 = __float_as_uint(v0.y), a3 = __float_as_uint(v1.y);
            int r0 = (8 * ks + tig) * 64, r1 = (8 * ks + tig + 4) * 64;
            float4 p0 = *(const float4*)&Vs[r0 + (((2 * g) ^ fswz) << 2)];
            float4 p1 = *(const float4*)&Vs[r0 + (((2 * g + 1) ^ fswz) << 2)];
            float4 q0 = *(const float4*)&Vs[r1 + (((2 * g) ^ fswz) << 2)];
            float4 q1 = *(const float4*)&Vs[r1 + (((2 * g + 1) ^ fswz) << 2)];
            unsigned b0[8], b1[8];
            b0[0] = __float_as_uint(p0.x); b0[1] = __float_as_uint(p0.y);
            b0[2] = __float_as_uint(p0.z); b0[3] = __float_as_uint(p0.w);
            b0[4] = __float_as_uint(p1.x); b0[5] = __float_as_uint(p1.y);
            b0[6] = __float_as_uint(p1.z); b0[7] = __float_as_uint(p1.w);
            b1[0] = __float_as_uint(q0.x); b1[1] = __float_as_uint(q0.y);
            b1[2] = __float_as_uint(q0.z); b1[3] = __float_as_uint(q0.w);
            b1[4] = __float_as_uint(q1.x); b1[5] = __float_as_uint(q1.y);
            b1[6] = __float_as_uint(q1.z); b1[7] = __float_as_uint(q1.w);
#pragma unroll
            for (int a = 0; a < 8; a++)
                mma_tf32(O[a], a0, a1, a2, a3, b0[a], b1[a]);
        }
    }

    // epilogue: normalize, write y (head-interleaved)
    float inv0 = 1.0f / lr[0], inv1 = 1.0f / lr[1];
#pragma unroll
    for (int a = 0; a < 8; a++) {
        int d = 8 * a + 2 * tig;
        float2 o0 = {O[a][0] * inv0, O[a][1] * inv0};
        float2 o1 = {O[a][2] * inv1, O[a][3] * inv1};
        *(float2*)&yout[(size_t)(b * TT + irow[0]) * CC + h * 64 + d] = o0;
        *(float2*)&yout[(size_t)(b * TT + irow[1]) * CC + h * 64 + d] = o1;
    }
}

// ---------------------------------------------------------------------------
__global__ void loss_kernel(const float* __restrict__ sp, const float* __restrict__ pw,
                            const float* __restrict__ rw, float* __restrict__ out,
                            int out_size)
{
    if (threadIdx.x == 0 && blockIdx.x == 0 && out_size > YELEMS) {
        float a = 0.0f;
        for (int h = 0; h < HH; h++) {
            float span   = 2048.0f / (1.0f + expf(-sp[h]));
            float period = 2.0f + 2.0f / (1.0f + expf(-pw[h]));
            float ratio  = -0.25f + 0.5f / (1.0f + expf(-rw[h]));
            float lt = 1.0f / period + 2.0f * ratio - 0.25f + 0.5f;
            a += (span + 32.0f) * lt;
        }
        out[YELEMS] = 2e-6f * a / (float)HH;
    }
}

// ---------------------------------------------------------------------------
extern "C" void kernel_launch(void* const* d_in, const int* in_sizes, int n_in,
                              void* d_out, int out_size)
{
    const float* x       = (const float*)d_in[0];
    const float* w_attn  = (const float*)d_in[1];
    const float* b_attn  = (const float*)d_in[2];
    const float* w_proj  = (const float*)d_in[3];
    const float* b_proj  = (const float*)d_in[4];
    const float* span_p  = (const float*)d_in[5];
    const float* per_w   = (const float*)d_in[6];
    const float* rat_w   = (const float*)d_in[7];
    float* out = (float*)d_out;

    float *qkvp = nullptr, *yattp = nullptr, *maskp = nullptr;
    cudaGetSymbolAddress((void**)&qkvp, g_qkv);
    cudaGetSymbolAddress((void**)&yattp, g_yatt);
    cudaGetSymbolAddress((void**)&maskp, g_mask);

    const int ATTN_SMEM = (BQ * QPSTR + 64 * 64 * 2 + TT) * (int)sizeof(float); // 77824
    cudaFuncSetAttribute(attn_mma, cudaFuncAttributeMaxDynamicSharedMemorySize, ATTN_SMEM);

    // 0. mask table
    maskgen<<<HH, 256>>>(span_p, per_w, rat_w, maskp);
    // 1. QKV projection (tf32 tensor cores)
    mma_gemm_bias<<<dim3(C3 / 128, MM / 128), 256>>>(x, w_attn, b_attn, qkvp, MM, C3, CC);
    // 2. attention (tf32 tensor cores + table mask + FFMA exp)
    attn_mma<<<dim3(TT / BQ, HH, BB), 256, ATTN_SMEM>>>(qkvp, span_p, maskp, yattp);
    // 3. output projection
    mma_gemm_bias<<<dim3(CC / 128, MM / 128), 256>>>(yattp, w_proj, b_proj, out, MM, CC, CC);
    // 4. span loss scalar
    loss_kernel<<<1, 32>>>(span_p, per_w, rat_w, out, out_size);
}